// round 6
// baseline (speedup 1.0000x reference)
#include <cuda_runtime.h>

// out[b] = dot(user_factors[users[b]], item_factors[items[b]]), D = 64, fp32.
//
// 256 CTAs x 256 threads, 8 elements per warp.
//  - Each lane directly loads the 8 indices it needs (warp-uniform addresses
//    -> L1 broadcast, ~2 lines total); no predication, no SHFL broadcast stage.
//  - 8 front-batched warp-wide LDG.128 row loads: 16 lanes cover one 64-float
//    row, so each load fetches TWO rows (elements 2p and 2p+1). MLP=8.
//  - 4 interleaved 16-lane butterfly reductions (4 rounds each).

#define D 64
#define ELEMS_PER_WARP 8
#define WARPS_PER_BLOCK 8
#define THREADS (WARPS_PER_BLOCK * 32)

__global__ __launch_bounds__(THREADS)
void mf_dot_kernel(const int* __restrict__ users,
                   const int* __restrict__ items,
                   const float* __restrict__ user_factors,
                   const float* __restrict__ item_factors,
                   float* __restrict__ out)
{
    const int warp_id = (blockIdx.x * WARPS_PER_BLOCK) + (threadIdx.x >> 5);
    const int lane = threadIdx.x & 31;
    const int half = lane >> 4;      // 0: even elements, 1: odd elements
    const int sub  = lane & 15;      // float4 chunk within a row
    const int base = warp_id * ELEMS_PER_WARP;

    // ---- Stage 1: direct index loads (all 8 per lane; broadcast in L1) ----
    int uidx0 = __ldg(&users[base + 0 + half]);
    int iidx0 = __ldg(&items[base + 0 + half]);
    int uidx1 = __ldg(&users[base + 2 + half]);
    int iidx1 = __ldg(&items[base + 2 + half]);
    int uidx2 = __ldg(&users[base + 4 + half]);
    int iidx2 = __ldg(&items[base + 4 + half]);
    int uidx3 = __ldg(&users[base + 6 + half]);
    int iidx3 = __ldg(&items[base + 6 + half]);

    // ---- Stage 2: 8 independent LDG.128 row loads, front-batched (MLP=8) ----
    const float4* ua0 = reinterpret_cast<const float4*>(user_factors + (long long)uidx0 * D);
    const float4* va0 = reinterpret_cast<const float4*>(item_factors + (long long)iidx0 * D);
    const float4* ua1 = reinterpret_cast<const float4*>(user_factors + (long long)uidx1 * D);
    const float4* va1 = reinterpret_cast<const float4*>(item_factors + (long long)iidx1 * D);
    const float4* ua2 = reinterpret_cast<const float4*>(user_factors + (long long)uidx2 * D);
    const float4* va2 = reinterpret_cast<const float4*>(item_factors + (long long)iidx2 * D);
    const float4* ua3 = reinterpret_cast<const float4*>(user_factors + (long long)uidx3 * D);
    const float4* va3 = reinterpret_cast<const float4*>(item_factors + (long long)iidx3 * D);

    float4 a0 = __ldg(&ua0[sub]);
    float4 b0 = __ldg(&va0[sub]);
    float4 a1 = __ldg(&ua1[sub]);
    float4 b1 = __ldg(&va1[sub]);
    float4 a2 = __ldg(&ua2[sub]);
    float4 b2 = __ldg(&va2[sub]);
    float4 a3 = __ldg(&ua3[sub]);
    float4 b3 = __ldg(&va3[sub]);

    // ---- Stage 3: per-lane dot4, then 4 interleaved 16-lane reductions ----
    float acc0 = a0.x * b0.x;
    acc0 = fmaf(a0.y, b0.y, acc0); acc0 = fmaf(a0.z, b0.z, acc0); acc0 = fmaf(a0.w, b0.w, acc0);
    float acc1 = a1.x * b1.x;
    acc1 = fmaf(a1.y, b1.y, acc1); acc1 = fmaf(a1.z, b1.z, acc1); acc1 = fmaf(a1.w, b1.w, acc1);
    float acc2 = a2.x * b2.x;
    acc2 = fmaf(a2.y, b2.y, acc2); acc2 = fmaf(a2.z, b2.z, acc2); acc2 = fmaf(a2.w, b2.w, acc2);
    float acc3 = a3.x * b3.x;
    acc3 = fmaf(a3.y, b3.y, acc3); acc3 = fmaf(a3.z, b3.z, acc3); acc3 = fmaf(a3.w, b3.w, acc3);

    #pragma unroll
    for (int off = 8; off > 0; off >>= 1) {
        acc0 += __shfl_xor_sync(0xFFFFFFFFu, acc0, off);
        acc1 += __shfl_xor_sync(0xFFFFFFFFu, acc1, off);
        acc2 += __shfl_xor_sync(0xFFFFFFFFu, acc2, off);
        acc3 += __shfl_xor_sync(0xFFFFFFFFu, acc3, off);
    }

    // ---- Stage 4: lanes 0 and 16 store 4 results each (same 32B region) ----
    if (sub == 0) {
        out[base + 0 + half] = acc0;
        out[base + 2 + half] = acc1;
        out[base + 4 + half] = acc2;
        out[base + 6 + half] = acc3;
    }
}

extern "C" void kernel_launch(void* const* d_in, const int* in_sizes, int n_in,
                              void* d_out, int out_size)
{
    const int*   users        = (const int*)  d_in[0];
    const int*   items        = (const int*)  d_in[1];
    const float* user_factors = (const float*)d_in[2];
    const float* item_factors = (const float*)d_in[3];
    float*       out          = (float*)      d_out;

    int batch = in_sizes[0];                       // 16384
    int warps = batch / ELEMS_PER_WARP;            // 2048
    int blocks = warps / WARPS_PER_BLOCK;          // 256
    mf_dot_kernel<<<blocks, THREADS>>>(users, items, user_factors, item_factors, out);
}

// round 7
// speedup vs baseline: 1.0097x; 1.0097x over previous
#include <cuda_runtime.h>

// out[b] = dot(user_factors[users[b]], item_factors[items[b]]), D = 64, fp32.
//
// 128 CTAs x 256 threads, 16 elements per warp.
//  - Lane-uniform direct index loads (L1 broadcast, 4 lines per warp total).
//  - 16 front-batched warp-wide LDG.128 row loads: 16 lanes cover one 64-float
//    row, each load fetches TWO rows (elements 2p and 2p+1). MLP=16 (~8KB in
//    flight per warp, under the ~55-outstanding cap).
//  - 8 interleaved 16-lane butterfly reductions (4 rounds each).

#define D 64
#define ELEMS_PER_WARP 16
#define PAIRS (ELEMS_PER_WARP / 2)
#define WARPS_PER_BLOCK 8
#define THREADS (WARPS_PER_BLOCK * 32)

__global__ __launch_bounds__(THREADS)
void mf_dot_kernel(const int* __restrict__ users,
                   const int* __restrict__ items,
                   const float* __restrict__ user_factors,
                   const float* __restrict__ item_factors,
                   float* __restrict__ out)
{
    const int warp_id = (blockIdx.x * WARPS_PER_BLOCK) + (threadIdx.x >> 5);
    const int lane = threadIdx.x & 31;
    const int half = lane >> 4;      // 0: even element of the pair, 1: odd
    const int sub  = lane & 15;      // float4 chunk within a row
    const int base = warp_id * ELEMS_PER_WARP;

    // ---- Stage 1: index loads (uniform per warp -> L1 broadcast) ----
    int uidx[PAIRS], iidx[PAIRS];
    #pragma unroll
    for (int p = 0; p < PAIRS; p++) {
        uidx[p] = __ldg(&users[base + 2 * p + half]);
        iidx[p] = __ldg(&items[base + 2 * p + half]);
    }

    // ---- Stage 2: 16 independent LDG.128 row loads, front-batched ----
    float4 a[PAIRS], b[PAIRS];
    #pragma unroll
    for (int p = 0; p < PAIRS; p++) {
        const float4* up = reinterpret_cast<const float4*>(
            user_factors + (long long)uidx[p] * D);
        const float4* vp = reinterpret_cast<const float4*>(
            item_factors + (long long)iidx[p] * D);
        a[p] = __ldg(&up[sub]);
        b[p] = __ldg(&vp[sub]);
    }

    // ---- Stage 3: per-lane dot4, then 8 interleaved 16-lane reductions ----
    float acc[PAIRS];
    #pragma unroll
    for (int p = 0; p < PAIRS; p++) {
        float t = a[p].x * b[p].x;
        t = fmaf(a[p].y, b[p].y, t);
        t = fmaf(a[p].z, b[p].z, t);
        t = fmaf(a[p].w, b[p].w, t);
        acc[p] = t;
    }

    #pragma unroll
    for (int off = 8; off > 0; off >>= 1) {
        #pragma unroll
        for (int p = 0; p < PAIRS; p++)
            acc[p] += __shfl_xor_sync(0xFFFFFFFFu, acc[p], off);
    }

    // ---- Stage 4: lanes 0 and 16 store 8 results each ----
    if (sub == 0) {
        #pragma unroll
        for (int p = 0; p < PAIRS; p++)
            out[base + 2 * p + half] = acc[p];
    }
}

extern "C" void kernel_launch(void* const* d_in, const int* in_sizes, int n_in,
                              void* d_out, int out_size)
{
    const int*   users        = (const int*)  d_in[0];
    const int*   items        = (const int*)  d_in[1];
    const float* user_factors = (const float*)d_in[2];
    const float* item_factors = (const float*)d_in[3];
    float*       out          = (float*)      d_out;

    int batch = in_sizes[0];                        // 16384
    int warps = batch / ELEMS_PER_WARP;             // 1024
    int blocks = warps / WARPS_PER_BLOCK;           // 128
    mf_dot_kernel<<<blocks, THREADS>>>(users, items, user_factors, item_factors, out);
}

// round 8
// speedup vs baseline: 1.0505x; 1.0404x over previous
#include <cuda_runtime.h>

// out[b] = dot(user_factors[users[b]], item_factors[items[b]]), D = 64, fp32.
//
// Best-measured shape (R5): 256 CTAs x 256 threads, 8 elements per warp.
//  - Lane-uniform direct index loads (L1 broadcast, ~2 lines per warp).
//  - 8 front-batched warp-wide LDG.128 row loads: 16 lanes cover one 64-float
//    row, each load fetches TWO rows (elements 2p and 2p+1). MLP=8.
//  - 32-bit byte-offset address math (tables < 256 MB) -> no IMAD.WIDE on the
//    idx -> address -> LDG critical chain.
//  - 4 interleaved 16-lane butterfly reductions (4 rounds each).

#define D 64
#define ROW_BYTES 256u           // D * sizeof(float)
#define ELEMS_PER_WARP 8
#define WARPS_PER_BLOCK 8
#define THREADS (WARPS_PER_BLOCK * 32)

__global__ __launch_bounds__(THREADS)
void mf_dot_kernel(const int* __restrict__ users,
                   const int* __restrict__ items,
                   const float* __restrict__ user_factors,
                   const float* __restrict__ item_factors,
                   float* __restrict__ out)
{
    const int warp_id = (blockIdx.x * WARPS_PER_BLOCK) + (threadIdx.x >> 5);
    const int lane = threadIdx.x & 31;
    const int half = lane >> 4;          // 0: even element of pair, 1: odd
    const unsigned sub16 = (lane & 15) * 16u;  // byte offset of this lane's float4
    const int base = warp_id * ELEMS_PER_WARP;

    const char* ubase = reinterpret_cast<const char*>(user_factors);
    const char* vbase = reinterpret_cast<const char*>(item_factors);

    // ---- Stage 1: index loads (uniform per warp -> L1 broadcast) ----
    unsigned uidx0 = (unsigned)__ldg(&users[base + 0 + half]);
    unsigned iidx0 = (unsigned)__ldg(&items[base + 0 + half]);
    unsigned uidx1 = (unsigned)__ldg(&users[base + 2 + half]);
    unsigned iidx1 = (unsigned)__ldg(&items[base + 2 + half]);
    unsigned uidx2 = (unsigned)__ldg(&users[base + 4 + half]);
    unsigned iidx2 = (unsigned)__ldg(&items[base + 4 + half]);
    unsigned uidx3 = (unsigned)__ldg(&users[base + 6 + half]);
    unsigned iidx3 = (unsigned)__ldg(&items[base + 6 + half]);

    // ---- Stage 2: 8 independent LDG.128 row loads (32-bit offsets) ----
    float4 a0 = __ldg(reinterpret_cast<const float4*>(ubase + uidx0 * ROW_BYTES + sub16));
    float4 b0 = __ldg(reinterpret_cast<const float4*>(vbase + iidx0 * ROW_BYTES + sub16));
    float4 a1 = __ldg(reinterpret_cast<const float4*>(ubase + uidx1 * ROW_BYTES + sub16));
    float4 b1 = __ldg(reinterpret_cast<const float4*>(vbase + iidx1 * ROW_BYTES + sub16));
    float4 a2 = __ldg(reinterpret_cast<const float4*>(ubase + uidx2 * ROW_BYTES + sub16));
    float4 b2 = __ldg(reinterpret_cast<const float4*>(vbase + iidx2 * ROW_BYTES + sub16));
    float4 a3 = __ldg(reinterpret_cast<const float4*>(ubase + uidx3 * ROW_BYTES + sub16));
    float4 b3 = __ldg(reinterpret_cast<const float4*>(vbase + iidx3 * ROW_BYTES + sub16));

    // ---- Stage 3: per-lane dot4, then 4 interleaved 16-lane reductions ----
    float acc0 = a0.x * b0.x;
    acc0 = fmaf(a0.y, b0.y, acc0); acc0 = fmaf(a0.z, b0.z, acc0); acc0 = fmaf(a0.w, b0.w, acc0);
    float acc1 = a1.x * b1.x;
    acc1 = fmaf(a1.y, b1.y, acc1); acc1 = fmaf(a1.z, b1.z, acc1); acc1 = fmaf(a1.w, b1.w, acc1);
    float acc2 = a2.x * b2.x;
    acc2 = fmaf(a2.y, b2.y, acc2); acc2 = fmaf(a2.z, b2.z, acc2); acc2 = fmaf(a2.w, b2.w, acc2);
    float acc3 = a3.x * b3.x;
    acc3 = fmaf(a3.y, b3.y, acc3); acc3 = fmaf(a3.z, b3.z, acc3); acc3 = fmaf(a3.w, b3.w, acc3);

    #pragma unroll
    for (int off = 8; off > 0; off >>= 1) {
        acc0 += __shfl_xor_sync(0xFFFFFFFFu, acc0, off);
        acc1 += __shfl_xor_sync(0xFFFFFFFFu, acc1, off);
        acc2 += __shfl_xor_sync(0xFFFFFFFFu, acc2, off);
        acc3 += __shfl_xor_sync(0xFFFFFFFFu, acc3, off);
    }

    // ---- Stage 4: lanes 0 and 16 store 4 results each (same 32B region) ----
    if ((lane & 15) == 0) {
        out[base + 0 + half] = acc0;
        out[base + 2 + half] = acc1;
        out[base + 4 + half] = acc2;
        out[base + 6 + half] = acc3;
    }
}

extern "C" void kernel_launch(void* const* d_in, const int* in_sizes, int n_in,
                              void* d_out, int out_size)
{
    const int*   users        = (const int*)  d_in[0];
    const int*   items        = (const int*)  d_in[1];
    const float* user_factors = (const float*)d_in[2];
    const float* item_factors = (const float*)d_in[3];
    float*       out          = (float*)      d_out;

    int batch = in_sizes[0];                       // 16384
    int warps = batch / ELEMS_PER_WARP;            // 2048
    int blocks = warps / WARPS_PER_BLOCK;          // 256
    mf_dot_kernel<<<blocks, THREADS>>>(users, items, user_factors, item_factors, out);
}